// round 1
// baseline (speedup 1.0000x reference)
#include <cuda_runtime.h>

// ---------------------------------------------------------------------------
// HospitalStaffingModel: fused 4-layer MLP + BN-fold + range masking.
// Round 1: exact fp32, packed fma.rn.f32x2 (2 rows per lane-register).
// ---------------------------------------------------------------------------

#define B_TOTAL 131072
#define D_IN    64
#define H1N     512
#define H2N     256
#define NCC     128
#define DCC     128
#define TM      32          // rows per CTA
#define RPAIRS  16          // row pairs per CTA
#define NT      256
#define EPSV    1e-5f
#define NEGV    -1e9f

typedef unsigned long long ull;

__device__ __forceinline__ ull pack2(float lo, float hi) {
    ull r; asm("mov.b64 %0, {%1,%2};" : "=l"(r) : "f"(lo), "f"(hi)); return r;
}
__device__ __forceinline__ void unpack2(ull v, float& lo, float& hi) {
    asm("mov.b64 {%0,%1}, %2;" : "=f"(lo), "=f"(hi) : "l"(v));
}
// Packed dual-fp32 FMA (sm_100+): d = a*b + c on both 32-bit halves.
__device__ __forceinline__ ull ffma2(ull a, ull b, ull c) {
    ull d; asm("fma.rn.f32x2 %0, %1, %2, %3;" : "=l"(d) : "l"(a), "l"(b), "l"(c)); return d;
}
__device__ __forceinline__ ull dup2(float v) { return pack2(v, v); }

// Dynamic SMEM layout (in ull units):
//   [0,      1024)  xs  : [16 rp][64 k]      (phase 0/1)   -- reused as n1s in phase 3
//   [1024,   9216)  h1s : [16 rp][512 c]     (phase 1/2)   -- first 1024 reused as d1s
//   [9216,  13312)  h2s : [16 rp][256 c]     (phase 2/3)
#define SMEM_ULL 13312
#define SMEM_BYTES (SMEM_ULL * 8)

__global__ __launch_bounds__(NT, 2)
void hosp_fused_kernel(
    const float* __restrict__ x,
    const float* __restrict__ W0,  const float* __restrict__ b0,
    const float* __restrict__ g0,  const float* __restrict__ be0,
    const float* __restrict__ rm0, const float* __restrict__ rv0,
    const float* __restrict__ W1,  const float* __restrict__ b1,
    const float* __restrict__ g1,  const float* __restrict__ be1,
    const float* __restrict__ rm1, const float* __restrict__ rv1,
    const float* __restrict__ nW1, const float* __restrict__ nb1,
    const float* __restrict__ nW2, const float* __restrict__ nb2,
    const float* __restrict__ dW1, const float* __restrict__ db1,
    const float* __restrict__ dW2, const float* __restrict__ db2,
    float* __restrict__ out)
{
    extern __shared__ ull sm[];
    ull* xs  = sm;              // [RPAIRS][64]
    ull* h1s = sm + 1024;       // [RPAIRS][512]
    ull* h2s = sm + 9216;       // [RPAIRS][256]
    ull* n1s = sm;              // [RPAIRS][64]  (reuse xs)
    ull* d1s = sm + 1024;       // [RPAIRS][64]  (reuse h1s head)

    __shared__ int sn[TM];
    __shared__ int sd[TM];

    const int tid = threadIdx.x;
    const int r0  = blockIdx.x * TM;

    // ---------------- Phase 0: load x tile (row-pair packed) + masks --------
    for (int i = tid; i < TM * D_IN; i += NT) {
        const int row = i >> 6;
        const int k   = i & 63;
        const float v = x[(size_t)(r0 + row) * D_IN + k];
        reinterpret_cast<float*>(xs)[(((row >> 1) * 64 + k) << 1) + (row & 1)] = v;
    }
    if (tid < TM) {
        sn[tid] = (int)x[(size_t)(r0 + tid) * D_IN + 60];   // column -4
    } else if (tid < 2 * TM) {
        const int r = tid - TM;
        sd[r] = (int)x[(size_t)(r0 + r) * D_IN + 61];       // column -3
    }
    __syncthreads();

    // ---------------- Phase 1: h1 = relu(bn0(x @ W0 + b0))  [32 x 512] ------
    {
        const int cg  = tid & 127;        // 4 cols each: [4cg, 4cg+4)
        const int rpb = (tid >> 7) * 8;   // 8 row-pairs
        const int c4  = cg << 2;

        ull acc[8][4];
        #pragma unroll
        for (int r = 0; r < 8; r++)
            #pragma unroll
            for (int c = 0; c < 4; c++) acc[r][c] = 0ULL;

        #pragma unroll 2
        for (int k = 0; k < D_IN; k++) {
            const float4 w = *reinterpret_cast<const float4*>(W0 + (size_t)k * H1N + c4);
            const ull w0 = dup2(w.x), w1 = dup2(w.y), w2 = dup2(w.z), w3 = dup2(w.w);
            #pragma unroll
            for (int r = 0; r < 8; r++) {
                const ull p = xs[(rpb + r) * 64 + k];
                acc[r][0] = ffma2(p, w0, acc[r][0]);
                acc[r][1] = ffma2(p, w1, acc[r][1]);
                acc[r][2] = ffma2(p, w2, acc[r][2]);
                acc[r][3] = ffma2(p, w3, acc[r][3]);
            }
        }
        #pragma unroll
        for (int c = 0; c < 4; c++) {
            const int j = c4 + c;
            const float s  = g0[j] * rsqrtf(rv0[j] + EPSV);
            const float bb = (b0[j] - rm0[j]) * s + be0[j];
            #pragma unroll
            for (int r = 0; r < 8; r++) {
                float lo, hi; unpack2(acc[r][c], lo, hi);
                lo = fmaxf(fmaf(lo, s, bb), 0.0f);
                hi = fmaxf(fmaf(hi, s, bb), 0.0f);
                h1s[(rpb + r) * H1N + j] = pack2(lo, hi);
            }
        }
    }
    __syncthreads();

    // ---------------- Phase 2: h2 = relu(bn1(h1 @ W1 + b1)) [32 x 256] ------
    {
        const int cg  = tid & 63;         // 4 cols each of 256
        const int rpb = (tid >> 6) * 4;   // 4 row-pairs
        const int c4  = cg << 2;

        ull acc[4][4];
        #pragma unroll
        for (int r = 0; r < 4; r++)
            #pragma unroll
            for (int c = 0; c < 4; c++) acc[r][c] = 0ULL;

        #pragma unroll 4
        for (int k = 0; k < H1N; k++) {
            const float4 w = *reinterpret_cast<const float4*>(W1 + (size_t)k * H2N + c4);
            const ull w0 = dup2(w.x), w1 = dup2(w.y), w2 = dup2(w.z), w3 = dup2(w.w);
            #pragma unroll
            for (int r = 0; r < 4; r++) {
                const ull p = h1s[(rpb + r) * H1N + k];
                acc[r][0] = ffma2(p, w0, acc[r][0]);
                acc[r][1] = ffma2(p, w1, acc[r][1]);
                acc[r][2] = ffma2(p, w2, acc[r][2]);
                acc[r][3] = ffma2(p, w3, acc[r][3]);
            }
        }
        #pragma unroll
        for (int c = 0; c < 4; c++) {
            const int j = c4 + c;
            const float s  = g1[j] * rsqrtf(rv1[j] + EPSV);
            const float bb = (b1[j] - rm1[j]) * s + be1[j];
            #pragma unroll
            for (int r = 0; r < 4; r++) {
                float lo, hi; unpack2(acc[r][c], lo, hi);
                lo = fmaxf(fmaf(lo, s, bb), 0.0f);
                hi = fmaxf(fmaf(hi, s, bb), 0.0f);
                h2s[(rpb + r) * H2N + j] = pack2(lo, hi);
            }
        }
    }
    __syncthreads();

    // ---------------- Phase 3a: n1/d1 = relu(h2 @ {n,d}W1 + b) [32 x 64] ----
    {
        const int cg = tid & 15;          // 4 cols each of 64
        const int rp = tid >> 4;          // one row-pair (16 total)
        const int c4 = cg << 2;

        ull na[4], da[4];
        #pragma unroll
        for (int c = 0; c < 4; c++) { na[c] = 0ULL; da[c] = 0ULL; }

        #pragma unroll 4
        for (int k = 0; k < H2N; k++) {
            const float4 wn = *reinterpret_cast<const float4*>(nW1 + (size_t)k * 64 + c4);
            const float4 wd = *reinterpret_cast<const float4*>(dW1 + (size_t)k * 64 + c4);
            const ull p = h2s[rp * H2N + k];
            na[0] = ffma2(p, dup2(wn.x), na[0]);
            na[1] = ffma2(p, dup2(wn.y), na[1]);
            na[2] = ffma2(p, dup2(wn.z), na[2]);
            na[3] = ffma2(p, dup2(wn.w), na[3]);
            da[0] = ffma2(p, dup2(wd.x), da[0]);
            da[1] = ffma2(p, dup2(wd.y), da[1]);
            da[2] = ffma2(p, dup2(wd.z), da[2]);
            da[3] = ffma2(p, dup2(wd.w), da[3]);
        }
        __syncthreads();   // everyone done reading h2s/xs before we overwrite n1s/d1s
        #pragma unroll
        for (int c = 0; c < 4; c++) {
            const int j = c4 + c;
            const float bn_ = nb1[j];
            const float bd_ = db1[j];
            float lo, hi;
            unpack2(na[c], lo, hi);
            n1s[rp * 64 + j] = pack2(fmaxf(lo + bn_, 0.0f), fmaxf(hi + bn_, 0.0f));
            unpack2(da[c], lo, hi);
            d1s[rp * 64 + j] = pack2(fmaxf(lo + bd_, 0.0f), fmaxf(hi + bd_, 0.0f));
        }
    }
    __syncthreads();

    // ---------------- Phase 3b: logits + bias + range mask + store ----------
    {
        const int cg  = tid & 31;         // 4 cols each of 128
        const int rpb = (tid >> 5) * 2;   // 2 row-pairs
        const int c4  = cg << 2;

        ull na[2][4], da[2][4];
        #pragma unroll
        for (int r = 0; r < 2; r++)
            #pragma unroll
            for (int c = 0; c < 4; c++) { na[r][c] = 0ULL; da[r][c] = 0ULL; }

        #pragma unroll 4
        for (int k = 0; k < 64; k++) {
            const float4 wn = *reinterpret_cast<const float4*>(nW2 + (size_t)k * NCC + c4);
            const float4 wd = *reinterpret_cast<const float4*>(dW2 + (size_t)k * DCC + c4);
            const ull wn0 = dup2(wn.x), wn1 = dup2(wn.y), wn2 = dup2(wn.z), wn3 = dup2(wn.w);
            const ull wd0 = dup2(wd.x), wd1 = dup2(wd.y), wd2 = dup2(wd.z), wd3 = dup2(wd.w);
            #pragma unroll
            for (int r = 0; r < 2; r++) {
                const ull pn = n1s[(rpb + r) * 64 + k];
                const ull pd = d1s[(rpb + r) * 64 + k];
                na[r][0] = ffma2(pn, wn0, na[r][0]);
                na[r][1] = ffma2(pn, wn1, na[r][1]);
                na[r][2] = ffma2(pn, wn2, na[r][2]);
                na[r][3] = ffma2(pn, wn3, na[r][3]);
                da[r][0] = ffma2(pd, wd0, da[r][0]);
                da[r][1] = ffma2(pd, wd1, da[r][1]);
                da[r][2] = ffma2(pd, wd2, da[r][2]);
                da[r][3] = ffma2(pd, wd3, da[r][3]);
            }
        }

        float bn_[4], bd_[4];
        #pragma unroll
        for (int c = 0; c < 4; c++) { bn_[c] = nb2[c4 + c]; bd_[c] = db2[c4 + c]; }

        float* outN = out;
        float* outD = out + (size_t)B_TOTAL * NCC;

        #pragma unroll
        for (int r = 0; r < 2; r++) {
            const int rp = rpb + r;
            const int rowE = 2 * rp;      // even row of the pair
            const int rowO = rowE + 1;
            const int snE = sn[rowE], snO = sn[rowO];
            const int sdE = sd[rowE], sdO = sd[rowO];

            float4 oNE, oNO, oDE, oDO;
            float* pNE = &oNE.x; float* pNO = &oNO.x;
            float* pDE = &oDE.x; float* pDO = &oDO.x;

            #pragma unroll
            for (int c = 0; c < 4; c++) {
                const int j = c4 + c;
                float lo, hi;
                unpack2(na[r][c], lo, hi);
                pNE[c] = (j <= snE) ? (lo + bn_[c]) : NEGV;
                pNO[c] = (j <= snO) ? (hi + bn_[c]) : NEGV;
                unpack2(da[r][c], lo, hi);
                pDE[c] = (j <= sdE) ? (lo + bd_[c]) : NEGV;
                pDO[c] = (j <= sdO) ? (hi + bd_[c]) : NEGV;
            }
            const size_t gRowE = (size_t)(r0 + rowE);
            const size_t gRowO = (size_t)(r0 + rowO);
            *reinterpret_cast<float4*>(outN + gRowE * NCC + c4) = oNE;
            *reinterpret_cast<float4*>(outN + gRowO * NCC + c4) = oNO;
            *reinterpret_cast<float4*>(outD + gRowE * DCC + c4) = oDE;
            *reinterpret_cast<float4*>(outD + gRowO * DCC + c4) = oDO;
        }
    }
}

extern "C" void kernel_launch(void* const* d_in, const int* in_sizes, int n_in,
                              void* d_out, int out_size)
{
    const float* x   = (const float*)d_in[0];
    const float* W0  = (const float*)d_in[1];
    const float* b0  = (const float*)d_in[2];
    const float* g0  = (const float*)d_in[3];
    const float* be0 = (const float*)d_in[4];
    const float* rm0 = (const float*)d_in[5];
    const float* rv0 = (const float*)d_in[6];
    const float* W1  = (const float*)d_in[7];
    const float* b1  = (const float*)d_in[8];
    const float* g1  = (const float*)d_in[9];
    const float* be1 = (const float*)d_in[10];
    const float* rm1 = (const float*)d_in[11];
    const float* rv1 = (const float*)d_in[12];
    const float* nW1 = (const float*)d_in[13];
    const float* nb1 = (const float*)d_in[14];
    const float* nW2 = (const float*)d_in[15];
    const float* nb2 = (const float*)d_in[16];
    const float* dW1 = (const float*)d_in[17];
    const float* db1 = (const float*)d_in[18];
    const float* dW2 = (const float*)d_in[19];
    const float* db2 = (const float*)d_in[20];

    cudaFuncSetAttribute(hosp_fused_kernel,
                         cudaFuncAttributeMaxDynamicSharedMemorySize, SMEM_BYTES);

    const int grid = B_TOTAL / TM;   // 4096
    hosp_fused_kernel<<<grid, NT, SMEM_BYTES>>>(
        x, W0, b0, g0, be0, rm0, rv0,
        W1, b1, g1, be1, rm1, rv1,
        nW1, nb1, nW2, nb2, dW1, db1, dW2, db2,
        (float*)d_out);
}